// round 8
// baseline (speedup 1.0000x reference)
#include <cuda_runtime.h>
#include <cstdint>

// Problem constants: B=512, T=256, C=384, HS=16
#define TT   256
#define CC   384
#define HSZ  16
#define KCH  32
#define NKC  (CC/KCH)    // 12
#define XP1  36          // proj x tile row stride (floats)
#define WSP  56          // proj W packed row stride (words)
#define QKP  20          // attn q/k row stride
#define VPD  20          // attn v row stride (conflict-free for 2*tig reads)

// ---- scratch (device globals; no allocations) ----
__device__ float g_q[512 * TT * HSZ];
__device__ float g_k[512 * TT * HSZ];
__device__ float g_v[512 * TT * HSZ];

// proj smem: 2 x (128*36 + 2*16*56) floats = 12800 f = 51200 B
#define PROJ_SMEM_FLOATS (2 * (128 * XP1 + 2 * 16 * WSP))
#define PROJ_SMEM_BYTES  (PROJ_SMEM_FLOATS * 4)
// attn smem: q 5120 + k 5120 + v 5120 + psum 256 + rinv 32 = 15648 f = 62592 B
#define ATTN_SMEM_FLOATS (3 * TT * QKP + 8 * 32 + 32)
#define ATTN_SMEM_BYTES  (ATTN_SMEM_FLOATS * 4)

__device__ __forceinline__ unsigned f2tf(float f) {
    unsigned r;
    asm("cvt.rna.tf32.f32 %0, %1;" : "=r"(r) : "f"(f));
    return r;
}
__device__ __forceinline__ unsigned pk2(float lo, float hi) {
    unsigned r;
    asm("cvt.rn.bf16x2.f32 %0, %1, %2;" : "=r"(r) : "f"(hi), "f"(lo));
    return r;
}
__device__ __forceinline__ float bflo(unsigned u) { return __uint_as_float(u << 16); }
__device__ __forceinline__ float bfhi(unsigned u) { return __uint_as_float(u & 0xffff0000u); }
__device__ __forceinline__ unsigned pkres(float lo, float hi, unsigned h) {
    return pk2(lo - bflo(h), hi - bfhi(h));
}

__device__ __forceinline__ void mma_tf32(float* c, const unsigned* a, const unsigned* b) {
    asm volatile(
        "mma.sync.aligned.m16n8k8.row.col.f32.tf32.tf32.f32 "
        "{%0,%1,%2,%3}, {%4,%5,%6,%7}, {%8,%9}, {%0,%1,%2,%3};"
        : "+f"(c[0]), "+f"(c[1]), "+f"(c[2]), "+f"(c[3])
        : "r"(a[0]), "r"(a[1]), "r"(a[2]), "r"(a[3]), "r"(b[0]), "r"(b[1]));
}
__device__ __forceinline__ void mma_bf16(float* c, const unsigned* a, const unsigned* b) {
    asm volatile(
        "mma.sync.aligned.m16n8k16.row.col.f32.bf16.bf16.f32 "
        "{%0,%1,%2,%3}, {%4,%5,%6,%7}, {%8,%9}, {%0,%1,%2,%3};"
        : "+f"(c[0]), "+f"(c[1]), "+f"(c[2]), "+f"(c[3])
        : "r"(a[0]), "r"(a[1]), "r"(a[2]), "r"(a[3]), "r"(b[0]), "r"(b[1]));
}
__device__ __forceinline__ void cpa16(uint32_t saddr, const float* g) {
    asm volatile("cp.async.ca.shared.global [%0], [%1], 16;" :: "r"(saddr), "l"(g));
}

// ====================== Kernel A: projection (streaming GEMM) ======================
// CTA c: batch c>>1, row half (c&1)*128. 8 warps x 16 rows. bf16 3-term.
__global__ void __launch_bounds__(256, 3) proj_kernel(
    const float* __restrict__ x,
    const float* __restrict__ wk,
    const float* __restrict__ wq,
    const float* __restrict__ wv)
{
    extern __shared__ float sm[];
    const int cta  = blockIdx.x;
    const int b    = cta >> 1;
    const int rbase = (cta & 1) * 128;
    const int tid  = threadIdx.x;
    const int lane = tid & 31;
    const int warp = tid >> 5;
    const int grp  = lane >> 2;
    const int tig  = lane & 3;
    const int r0w  = warp * 16;   // warp's row base within the 128-row half

    const uint32_t sm_base = (uint32_t)__cvta_generic_to_shared(sm);
    const float* xb = x + ((size_t)b * TT + rbase) * CC;

    float acc[6][4];
#pragma unroll
    for (int nt = 0; nt < 6; ++nt)
#pragma unroll
        for (int e = 0; e < 4; ++e) acc[nt][e] = 0.f;

    auto load_chunk = [&](int kc, int buf) {
        const float* xg = xb + kc * KCH;
        uint32_t xs_a = sm_base + (uint32_t)(buf * 128 * XP1) * 4u;
#pragma unroll
        for (int i = 0; i < 4; ++i) {
            int row = (tid >> 3) + i * 32;
            int c4  = (tid & 7) * 4;
            cpa16(xs_a + (uint32_t)(row * XP1 + c4) * 4u, xg + row * CC + c4);
        }
        unsigned* whd = reinterpret_cast<unsigned*>(sm + 2 * 128 * XP1 + buf * 2 * 16 * WSP);
        unsigned* wld = whd + 16 * WSP;
#pragma unroll
        for (int i = 0; i < 3; ++i) {
            int f  = tid + i * 256;
            int kp = f / 48, c = f % 48;
            int gk = kc * KCH + 2 * kp;
            const float* src = (c < 16) ? (wq + gk * HSZ + c)
                             : (c < 32) ? (wk + gk * HSZ + (c - 16))
                                        : (wv + gk * HSZ + (c - 32));
            float w0 = src[0];
            float w1 = src[HSZ];
            unsigned h = pk2(w0, w1);
            whd[kp * WSP + c] = h;
            wld[kp * WSP + c] = pkres(w0, w1, h);
        }
    };

    load_chunk(0, 0);
    asm volatile("cp.async.commit_group;");

    for (int kc = 0; kc < NKC; ++kc) {
        const int buf = kc & 1;
        if (kc + 1 < NKC) {
            load_chunk(kc + 1, buf ^ 1);
            asm volatile("cp.async.commit_group;");
            asm volatile("cp.async.wait_group 1;");
        } else {
            asm volatile("cp.async.wait_group 0;");
        }
        __syncthreads();

        const float* xs = sm + buf * 128 * XP1;
        const unsigned* wh = reinterpret_cast<const unsigned*>(
            sm + 2 * 128 * XP1 + buf * 2 * 16 * WSP);
        const unsigned* wl = wh + 16 * WSP;

#pragma unroll
        for (int ch = 0; ch < 2; ++ch) {
            const int ko = ch * 16;
            int rr = r0w + grp;
            float2 x0 = *reinterpret_cast<const float2*>(xs + rr * XP1 + ko + 2 * tig);
            float2 x1 = *reinterpret_cast<const float2*>(xs + (rr + 8) * XP1 + ko + 2 * tig);
            float2 x2 = *reinterpret_cast<const float2*>(xs + rr * XP1 + ko + 8 + 2 * tig);
            float2 x3 = *reinterpret_cast<const float2*>(xs + (rr + 8) * XP1 + ko + 8 + 2 * tig);
            unsigned ah[4], al[4];
            ah[0] = pk2(x0.x, x0.y); al[0] = pkres(x0.x, x0.y, ah[0]);
            ah[1] = pk2(x1.x, x1.y); al[1] = pkres(x1.x, x1.y, ah[1]);
            ah[2] = pk2(x2.x, x2.y); al[2] = pkres(x2.x, x2.y, ah[2]);
            ah[3] = pk2(x3.x, x3.y); al[3] = pkres(x3.x, x3.y, ah[3]);
#pragma unroll
            for (int nt = 0; nt < 6; ++nt) {
                int cb = nt * 8 + grp;
                unsigned bh[2], bl[2];
                bh[0] = wh[(ch * 8 + tig) * WSP + cb];
                bh[1] = wh[(ch * 8 + 4 + tig) * WSP + cb];
                bl[0] = wl[(ch * 8 + tig) * WSP + cb];
                bl[1] = wl[(ch * 8 + 4 + tig) * WSP + cb];
                mma_bf16(acc[nt], ah, bh);
                mma_bf16(acc[nt], ah, bl);
                mma_bf16(acc[nt], al, bh);
            }
        }
        __syncthreads();
    }

    // write qkv to global scratch (q scaled + tf32-rounded, k tf32-rounded, v raw)
    const float qscale = rsqrtf((float)CC);
    const int grow = b * TT + rbase + r0w + grp;   // global row (first of the pair)
#pragma unroll
    for (int nt = 0; nt < 6; ++nt) {
        int cgl = nt * 8 + 2 * tig;
        float e0 = acc[nt][0], e1 = acc[nt][1];   // row grow
        float e2 = acc[nt][2], e3 = acc[nt][3];   // row grow+8
        if (cgl < 16) {
            float2 a = make_float2(__uint_as_float(f2tf(e0 * qscale)),
                                   __uint_as_float(f2tf(e1 * qscale)));
            float2 c = make_float2(__uint_as_float(f2tf(e2 * qscale)),
                                   __uint_as_float(f2tf(e3 * qscale)));
            *reinterpret_cast<float2*>(g_q + (size_t)grow * HSZ + cgl) = a;
            *reinterpret_cast<float2*>(g_q + (size_t)(grow + 8) * HSZ + cgl) = c;
        } else if (cgl < 32) {
            float2 a = make_float2(__uint_as_float(f2tf(e0)), __uint_as_float(f2tf(e1)));
            float2 c = make_float2(__uint_as_float(f2tf(e2)), __uint_as_float(f2tf(e3)));
            *reinterpret_cast<float2*>(g_k + (size_t)grow * HSZ + (cgl - 16)) = a;
            *reinterpret_cast<float2*>(g_k + (size_t)(grow + 8) * HSZ + (cgl - 16)) = c;
        } else {
            *reinterpret_cast<float2*>(g_v + (size_t)grow * HSZ + (cgl - 32)) = make_float2(e0, e1);
            *reinterpret_cast<float2*>(g_v + (size_t)(grow + 8) * HSZ + (cgl - 32)) = make_float2(e2, e3);
        }
    }
}

// ====================== Kernel B: attention (column softmax) ======================
__global__ void __launch_bounds__(256, 3) attn_kernel(float* __restrict__ out)
{
    extern __shared__ float sm[];
    const int b    = blockIdx.x;
    const int tid  = threadIdx.x;
    const int lane = tid & 31;
    const int warp = tid >> 5;
    const int grp  = lane >> 2;
    const int tig  = lane & 3;

    float* q_s  = sm;
    float* k_s  = q_s + TT * QKP;
    float* v_s  = k_s + TT * QKP;
    float* psum = v_s + TT * VPD;
    float* rinv = psum + 8 * 32;

    // load qkv for this batch into smem (coalesced float4)
    {
        const float4* qg = reinterpret_cast<const float4*>(g_q + (size_t)b * TT * HSZ);
        const float4* kg = reinterpret_cast<const float4*>(g_k + (size_t)b * TT * HSZ);
        const float4* vg = reinterpret_cast<const float4*>(g_v + (size_t)b * TT * HSZ);
#pragma unroll
        for (int i = 0; i < 4; ++i) {
            int idx = tid + i * 256;            // 1024 float4 slots
            int row = idx >> 2, c4 = (idx & 3) * 4;
            float4 q4 = qg[idx];
            float4 k4 = kg[idx];
            float4 v4 = vg[idx];
            *reinterpret_cast<float4*>(q_s + row * QKP + c4) = q4;
            *reinterpret_cast<float4*>(k_s + row * QKP + c4) = k4;
            *reinterpret_cast<float4*>(v_s + row * VPD + c4) = v4;
        }
    }
    __syncthreads();

    const int rb0 = warp * 16;
    const int rb1 = 240 - warp * 16;
    int rb[2] = {rb0, rb1};

    float oacc[2][2][4];
#pragma unroll
    for (int mt = 0; mt < 2; ++mt)
#pragma unroll
        for (int nt = 0; nt < 2; ++nt)
#pragma unroll
            for (int e = 0; e < 4; ++e) oacc[mt][nt][e] = 0.f;

    for (int blk = 0; blk < TT / 32; ++blk) {
        const int s0 = blk * 32;
        const bool act0 = (warp >= 2 * blk);
        const bool act1 = ((15 - warp) >= 2 * blk);
        const bool anyact = act1;

        float ef[2][4][4];
#pragma unroll
        for (int mt = 0; mt < 2; ++mt)
#pragma unroll
            for (int nt = 0; nt < 4; ++nt)
#pragma unroll
                for (int e = 0; e < 4; ++e) ef[mt][nt][e] = 0.f;

        float ps[4][2];
#pragma unroll
        for (int nt = 0; nt < 4; ++nt) { ps[nt][0] = 0.f; ps[nt][1] = 0.f; }

        if (anyact) {
            // S = q k^T (K=16), tf32, operands pre-rounded
#pragma unroll
            for (int k8 = 0; k8 < 2; ++k8) {
                const int ko = k8 * 8;
                unsigned aq[2][4];
#pragma unroll
                for (int mt = 0; mt < 2; ++mt) {
                    if (mt == 0 && !act0) continue;
                    int r0 = rb[mt] + grp;
                    aq[mt][0] = __float_as_uint(q_s[r0 * QKP + ko + tig]);
                    aq[mt][1] = __float_as_uint(q_s[(r0 + 8) * QKP + ko + tig]);
                    aq[mt][2] = __float_as_uint(q_s[r0 * QKP + ko + tig + 4]);
                    aq[mt][3] = __float_as_uint(q_s[(r0 + 8) * QKP + ko + tig + 4]);
                }
#pragma unroll
                for (int nt = 0; nt < 4; ++nt) {
                    int sc = s0 + nt * 8 + grp;
                    unsigned bb[2];
                    bb[0] = __float_as_uint(k_s[sc * QKP + ko + tig]);
                    bb[1] = __float_as_uint(k_s[sc * QKP + ko + tig + 4]);
                    if (act0) mma_tf32(ef[0][nt], aq[0], bb);
                    mma_tf32(ef[1][nt], aq[1], bb);
                }
            }
            // mask + exp
#pragma unroll
            for (int mt = 0; mt < 2; ++mt) {
                if (mt == 0 && !act0) {
#pragma unroll
                    for (int nt = 0; nt < 4; ++nt)
#pragma unroll
                        for (int e = 0; e < 4; ++e) ef[0][nt][e] = 0.f;
                    continue;
                }
#pragma unroll
                for (int nt = 0; nt < 4; ++nt)
#pragma unroll
                    for (int e = 0; e < 4; ++e) {
                        int r  = rb[mt] + grp + ((e >= 2) ? 8 : 0);
                        int sg = s0 + nt * 8 + 2 * tig + (e & 1);
                        ef[mt][nt][e] = (sg <= r) ? __expf(ef[mt][nt][e]) : 0.f;
                    }
            }
            // per-column partial sums
#pragma unroll
            for (int nt = 0; nt < 4; ++nt)
#pragma unroll
                for (int bb2 = 0; bb2 < 2; ++bb2) {
                    float s = ef[0][nt][bb2] + ef[0][nt][bb2 + 2]
                            + ef[1][nt][bb2] + ef[1][nt][bb2 + 2];
                    s += __shfl_xor_sync(0xffffffffu, s, 4);
                    s += __shfl_xor_sync(0xffffffffu, s, 8);
                    s += __shfl_xor_sync(0xffffffffu, s, 16);
                    ps[nt][bb2] = s;
                }
        }
        if (grp == 0) {
#pragma unroll
            for (int nt = 0; nt < 4; ++nt) {
                psum[warp * 32 + nt * 8 + 2 * tig]     = ps[nt][0];
                psum[warp * 32 + nt * 8 + 2 * tig + 1] = ps[nt][1];
            }
        }
        __syncthreads();
        if (tid < 32) {
            float s = 0.f;
#pragma unroll
            for (int w = 0; w < 8; ++w) s += psum[w * 32 + tid];
            rinv[tid] = 1.0f / s;
        }
        __syncthreads();

        if (anyact) {
            // PV in bf16 3-term, k16 (C-frag == A-frag layout, no shuffles)
#pragma unroll
            for (int ch = 0; ch < 2; ++ch) {
                const int sb = s0 + ch * 16;
                unsigned pah[2][4], pal[2][4];
#pragma unroll
                for (int mt = 0; mt < 2; ++mt) {
                    if (mt == 0 && !act0) continue;
#pragma unroll
                    for (int hq = 0; hq < 2; ++hq) {
                        float e0 = ef[mt][2 * ch + hq][0];
                        float e1 = ef[mt][2 * ch + hq][1];
                        float e2 = ef[mt][2 * ch + hq][2];
                        float e3 = ef[mt][2 * ch + hq][3];
                        pah[mt][2 * hq]     = pk2(e0, e1);
                        pal[mt][2 * hq]     = pkres(e0, e1, pah[mt][2 * hq]);
                        pah[mt][2 * hq + 1] = pk2(e2, e3);
                        pal[mt][2 * hq + 1] = pkres(e2, e3, pah[mt][2 * hq + 1]);
                    }
                }
                float r0 = rinv[ch * 16 + 2 * tig];
                float r1 = rinv[ch * 16 + 2 * tig + 1];
                float r2 = rinv[ch * 16 + 8 + 2 * tig];
                float r3 = rinv[ch * 16 + 9 + 2 * tig];
#pragma unroll
                for (int nt = 0; nt < 2; ++nt) {
                    int d = nt * 8 + grp;
                    float b0 = v_s[(sb + 2 * tig)     * VPD + d] * r0;
                    float b1 = v_s[(sb + 2 * tig + 1) * VPD + d] * r1;
                    float b2 = v_s[(sb + 8 + 2 * tig) * VPD + d] * r2;
                    float b3 = v_s[(sb + 9 + 2 * tig) * VPD + d] * r3;
                    unsigned bh[2], bl[2];
                    bh[0] = pk2(b0, b1); bl[0] = pkres(b0, b1, bh[0]);
                    bh[1] = pk2(b2, b3); bl[1] = pkres(b2, b3, bh[1]);
                    if (act0) {
                        mma_bf16(oacc[0][nt], pah[0], bh);
                        mma_bf16(oacc[0][nt], pah[0], bl);
                        mma_bf16(oacc[0][nt], pal[0], bh);
                    }
                    mma_bf16(oacc[1][nt], pah[1], bh);
                    mma_bf16(oacc[1][nt], pah[1], bl);
                    mma_bf16(oacc[1][nt], pal[1], bh);
                }
            }
        }
    }

    float* ob = out + (size_t)b * TT * HSZ;
#pragma unroll
    for (int mt = 0; mt < 2; ++mt)
#pragma unroll
        for (int nt = 0; nt < 2; ++nt) {
            int r0 = rb[mt] + grp;
            int c  = nt * 8 + 2 * tig;
            *reinterpret_cast<float2*>(ob + r0 * HSZ + c) =
                make_float2(oacc[mt][nt][0], oacc[mt][nt][1]);
            *reinterpret_cast<float2*>(ob + (r0 + 8) * HSZ + c) =
                make_float2(oacc[mt][nt][2], oacc[mt][nt][3]);
        }
}

extern "C" void kernel_launch(void* const* d_in, const int* in_sizes, int n_in,
                              void* d_out, int out_size) {
    const float* x  = (const float*)d_in[0];
    const float* wk = (const float*)d_in[1];
    const float* wq = (const float*)d_in[2];
    const float* wv = (const float*)d_in[3];
    float* out      = (float*)d_out;

    const int B = in_sizes[0] / (TT * CC);  // 512

    cudaFuncSetAttribute(proj_kernel,
                         cudaFuncAttributeMaxDynamicSharedMemorySize, PROJ_SMEM_BYTES);
    cudaFuncSetAttribute(attn_kernel,
                         cudaFuncAttributeMaxDynamicSharedMemorySize, ATTN_SMEM_BYTES);

    proj_kernel<<<2 * B, 256, PROJ_SMEM_BYTES>>>(x, wk, wq, wv);
    attn_kernel<<<B, 256, ATTN_SMEM_BYTES>>>(out);
}